// round 16
// baseline (speedup 1.0000x reference)
#include <cuda_runtime.h>
#include <cuda_fp16.h>
#include <cstdint>

// ---------------------------------------------------------------- dims
#define B_N   2048
#define D_IN  2047
#define NIN   2048
#define K_N   4096
#define TABLE_MASK ((1 << 22) - 1)

#define BM 128
#define BN 64
#define BK 64
#define NCHUNK (NIN / BK)          // 32
#define XPLANE (B_N * NIN)
#define APLANE (K_N * NIN)

#define X_TILEB 16384              // 128 rows x 128 B
#define A_TILEB 8192               // 64 rows x 128 B
#define STAGEB (X_TILEB + A_TILEB) // 24576
#define NSTAGE 4
#define DYNSMEM (NSTAGE * STAGEB)  // 98304

#define TH   0.15f
#define FCAP 131072

// ---------------------------------------------------------------- scratch
// Pre-tiled, pre-swizzled fp16 operands:
//   byte(row, colh) = row*128 + (((colh>>3) ^ (row&7))<<4) + ((colh&7)<<1)
__device__ __align__(128) uint8_t g_Xt[16u * 32u * X_TILEB];  // 8 MB  [jt][ch][128x128B]
__device__ __align__(128) uint8_t g_At[64u * 32u * A_TILEB];  // 16 MB [kt][ch][64x128B]
__device__ int g_acc[B_N];
__device__ int g_nflag;
__device__ int g_flags[FCAP];

// ---------------------------------------------------------------- helpers
__device__ __forceinline__ uint32_t smem_u32(const void* p) {
    uint32_t a;
    asm("{ .reg .u64 t; cvta.to.shared.u64 t, %1; cvt.u32.u64 %0, t; }" : "=r"(a) : "l"(p));
    return a;
}
__device__ __forceinline__ void mbar_init(uint32_t mb, uint32_t cnt) {
    asm volatile("mbarrier.init.shared.b64 [%0], %1;" :: "r"(mb), "r"(cnt) : "memory");
}
__device__ __forceinline__ void mbar_expect_tx(uint32_t mb, uint32_t bytes) {
    asm volatile("mbarrier.arrive.expect_tx.shared.b64 _, [%0], %1;"
                 :: "r"(mb), "r"(bytes) : "memory");
}
__device__ __forceinline__ void mbar_wait(uint32_t mb, uint32_t parity) {
    asm volatile(
        "{\n\t.reg .pred P;\n"
        "W%=:\n\tmbarrier.try_wait.parity.shared.b64 P, [%0], %1;\n"
        "\t@!P bra W%=;\n\t}"
        :: "r"(mb), "r"(parity) : "memory");
}
__device__ __forceinline__ void bulk_g2s(uint32_t dst, const void* src,
                                         uint32_t bytes, uint32_t mb) {
    asm volatile(
        "cp.async.bulk.shared::cluster.global.mbarrier::complete_tx::bytes "
        "[%0], [%1], %2, [%3];"
        :: "r"(dst), "l"(src), "r"(bytes), "r"(mb) : "memory");
}
__device__ __forceinline__ void ldm_x4(uint32_t* r, uint32_t addr) {
    asm volatile("ldmatrix.sync.aligned.m8n8.x4.shared.b16 {%0,%1,%2,%3}, [%4];"
                 : "=r"(r[0]), "=r"(r[1]), "=r"(r[2]), "=r"(r[3]) : "r"(addr));
}
__device__ __forceinline__ void mma16816(float* d, const uint32_t* a, uint32_t b0, uint32_t b1) {
    asm volatile("mma.sync.aligned.m16n8k16.row.col.f32.f16.f16.f32 "
                 "{%0,%1,%2,%3},{%4,%5,%6,%7},{%8,%9},{%0,%1,%2,%3};"
                 : "+f"(d[0]), "+f"(d[1]), "+f"(d[2]), "+f"(d[3])
                 : "r"(a[0]), "r"(a[1]), "r"(a[2]), "r"(a[3]), "r"(b0), "r"(b1));
}

// ---------------------------------------------------------------- kernel 1: pack + fp16 convert into tiled/swizzled layout
#define XHALF (XPLANE / 2)
#define AOCT  (APLANE / 8)

__global__ __launch_bounds__(256) void split_kernel(const float* __restrict__ states,
                                                    const float* __restrict__ actions,
                                                    const float* __restrict__ A)
{
    unsigned t = blockIdx.x * 256u + threadIdx.x;
    if (t < B_N) g_acc[t] = 0;
    if (t == 0) g_nflag = 0;

    if (t < XHALF) {
        unsigned j  = t >> 10;
        unsigned d  = (t & 1023u) << 1;
        float f0 = states[j * D_IN + d];                               // d <= 2046
        float f1 = (d + 1 < D_IN) ? states[j * D_IN + d + 1] : actions[j];
        __half2 h = __halves2half2(__float2half_rn(f0), __float2half_rn(f1));
        unsigned jt = j >> 7, row = j & 127u;
        unsigned ch = d >> 6, colh = d & 63u;
        unsigned off = ((jt * 32u + ch) << 14)
                     + row * 128u
                     + (((colh >> 3) ^ (row & 7u)) << 4)
                     + ((colh & 7u) << 1);
        *(uint32_t*)(g_Xt + off) = *(uint32_t*)&h;
    } else {
        unsigned e = t - XHALF;
        if (e < AOCT) {
            unsigned k   = e >> 8;
            unsigned d8  = (e & 255u) << 3;
            const float4* src = (const float4*)(A + ((size_t)k << 11) + d8);
            float4 v0 = src[0], v1 = src[1];
            __half2 h0 = __halves2half2(__float2half_rn(v0.x), __float2half_rn(v0.y));
            __half2 h1 = __halves2half2(__float2half_rn(v0.z), __float2half_rn(v0.w));
            __half2 h2 = __halves2half2(__float2half_rn(v1.x), __float2half_rn(v1.y));
            __half2 h3 = __halves2half2(__float2half_rn(v1.z), __float2half_rn(v1.w));
            uint4 o;
            o.x = *(uint32_t*)&h0; o.y = *(uint32_t*)&h1;
            o.z = *(uint32_t*)&h2; o.w = *(uint32_t*)&h3;
            unsigned kt = k >> 6, row = k & 63u;      // 64-row A tiles now
            unsigned ch = d8 >> 6, u = (d8 >> 3) & 7u;
            unsigned off = ((kt * 32u + ch) << 13)
                         + row * 128u
                         + ((u ^ (row & 7u)) << 4);
            *(uint4*)(g_At + off) = o;
        }
    }
}

// ---------------------------------------------------------------- kernel 2: fp16 HMMA GEMM + sign + hash
// 128x64 tiles (grid 1024: smoother waves), 4-stage bulk-copy ring.
// Per-(j,k) k16 accumulation chain identical to R13/R14 -> bit-identical C.
__global__ __launch_bounds__(256, 2) void gemm_tc(const float* __restrict__ b,
                                                  const int*   __restrict__ hc)
{
    extern __shared__ __align__(128) unsigned char dynsmem[];
    __shared__ __align__(8) uint64_t s_mbar[NSTAGE];

    const uint32_t sbase = smem_u32(dynsmem);
    const uint32_t mb0   = smem_u32(&s_mbar[0]);

    const int tid  = threadIdx.x;
    const int wid  = tid >> 5;
    const int lane = tid & 31;
    const int wm   = wid & 1;          // 2 warps over M (64 rows each)
    const int wn   = wid >> 1;         // 4 warps over N (16 cols each)
    const int jt   = blockIdx.y;
    const int kt   = blockIdx.x;
    const int jBase = jt * BM;
    const int kBase = kt * BN;

    const int laneRow = (lane & 7) + ((lane >> 3) & 1) * 8;
    const int hi      = lane >> 4;     // 0/1: 16B-unit select within k16 slice

    float c[4][2][4];
    #pragma unroll
    for (int mi = 0; mi < 4; ++mi)
        #pragma unroll
        for (int ni = 0; ni < 2; ++ni)
            #pragma unroll
            for (int e = 0; e < 4; ++e) c[mi][ni][e] = 0.f;

    if (tid == 0) {
        #pragma unroll
        for (int s = 0; s < NSTAGE; ++s) mbar_init(mb0 + 8u * s, 1);
    }
    __syncthreads();
    if (tid == 0) asm volatile("fence.proxy.async.shared::cta;" ::: "memory");

    auto issue = [&](int ch, int s) {   // tid 0 only
        const uint32_t mb = mb0 + 8u * (uint32_t)s;
        const uint32_t dx = sbase + (uint32_t)s * STAGEB;
        mbar_expect_tx(mb, STAGEB);
        bulk_g2s(dx,           g_Xt + ((size_t)(jt * 32 + ch) << 14), X_TILEB, mb);
        bulk_g2s(dx + X_TILEB, g_At + ((size_t)(kt * 32 + ch) << 13), A_TILEB, mb);
    };

    if (tid == 0) { issue(0, 0); issue(1, 1); issue(2, 2); }

    for (int ch = 0; ch < NCHUNK; ++ch) {
        const int st = ch % NSTAGE;
        mbar_wait(mb0 + 8u * (uint32_t)st, (uint32_t)((ch / NSTAGE) & 1));
        __syncthreads();                          // all warps done with stage (ch-1)%4
        if (ch + 3 < NCHUNK && tid == 0)
            issue(ch + 3, (ch + 3) % NSTAGE);     // = stage (ch-1)%4, safe post-sync

        const uint32_t xt = sbase + (uint32_t)st * STAGEB;
        const uint32_t at = xt + X_TILEB;
        #pragma unroll
        for (int k16 = 0; k16 < 4; ++k16) {       // BK=64 -> 4 k16 slices, same global order
            const int u = k16 * 2 + hi;
            uint32_t af[4][4], bf[4];
            #pragma unroll
            for (int mi = 0; mi < 4; ++mi) {
                const int r = wm * 64 + mi * 16 + laneRow;
                ldm_x4(af[mi], xt + (uint32_t)(r * 128 + ((u ^ (r & 7)) << 4)));
            }
            {
                const int r = wn * 16 + laneRow;  // 16 n-rows for this warp
                ldm_x4(bf, at + (uint32_t)(r * 128 + ((u ^ (r & 7)) << 4)));
            }
            #pragma unroll
            for (int mi = 0; mi < 4; ++mi)
                #pragma unroll
                for (int ni = 0; ni < 2; ++ni)
                    mma16816(c[mi][ni], af[mi], bf[ni], bf[ni + 2]);
        }
    }

    // ---- epilogue: sign, hash-select, flag near-zero, reduce, atomic
    const int g  = lane >> 2;
    const int t4 = lane & 3;
    int khc[4];
    #pragma unroll
    for (int ni = 0; ni < 2; ++ni)
        #pragma unroll
        for (int e = 0; e < 2; ++e)
            khc[ni * 2 + e] = __ldg(&hc[kBase + wn * 16 + ni * 8 + t4 * 2 + e]);

    #pragma unroll
    for (int mi = 0; mi < 4; ++mi) {
        #pragma unroll
        for (int half = 0; half < 2; ++half) {
            const int j = jBase + wm * 64 + mi * 16 + half * 8 + g;
            const float bias = __ldg(&b[j]);
            int local = 0;
            #pragma unroll
            for (int ni = 0; ni < 2; ++ni) {
                #pragma unroll
                for (int e = 0; e < 2; ++e) {
                    const float v = c[mi][ni][half * 2 + e] + bias;
                    const int bit = v > 0.f;
                    if (bit) local += khc[ni * 2 + e];
                    if (fabsf(v) < TH) {
                        const int k = kBase + wn * 16 + ni * 8 + t4 * 2 + e;
                        int slot = atomicAdd(&g_nflag, 1);
                        if (slot < FCAP) g_flags[slot] = (j << 13) | (k << 1) | bit;
                    }
                }
            }
            local += __shfl_xor_sync(0xFFFFFFFFu, local, 1);
            local += __shfl_xor_sync(0xFFFFFFFFu, local, 2);
            if (t4 == 0) atomicAdd(&g_acc[j], local);
        }
    }
}

// ---------------------------------------------------------------- kernel 3: exact fp32 fixup (same fmaf order as the rel_err=0.0 runs)
__global__ __launch_bounds__(256) void fixup_kernel(const float* __restrict__ states,
                                                    const float* __restrict__ actions,
                                                    const float* __restrict__ A,
                                                    const float* __restrict__ b,
                                                    const int*   __restrict__ hc)
{
    const int lane = threadIdx.x & 31;
    const int w    = (blockIdx.x * blockDim.x + threadIdx.x) >> 5;
    const int nw   = (gridDim.x * blockDim.x) >> 5;
    int n = g_nflag;
    if (n > FCAP) n = FCAP;

    for (int e = w; e < n; e += nw) {
        const int f  = g_flags[e];
        const int j  = f >> 13;
        const int k  = (f >> 1) & 0xFFF;
        const int ob = f & 1;
        const float*  xr = states + (size_t)j * D_IN;
        const float4* ar = (const float4*)(A + (size_t)k * NIN);
        const float   act = actions[j];
        float s = 0.f;
        #pragma unroll 4
        for (int d = lane; d < NIN / 4; d += 32) {
            const int dd = d << 2;
            float4 av = ar[d];
            float x0 = xr[dd + 0];
            float x1 = xr[dd + 1];
            float x2 = xr[dd + 2];
            float x3 = (dd + 3 < D_IN) ? xr[dd + 3] : act;
            s = fmaf(x0, av.x, s);
            s = fmaf(x1, av.y, s);
            s = fmaf(x2, av.z, s);
            s = fmaf(x3, av.w, s);
        }
        #pragma unroll
        for (int o = 16; o; o >>= 1) s += __shfl_xor_sync(0xFFFFFFFFu, s, o);
        if (lane == 0) {
            const int nb = (s + b[j]) > 0.f;
            if (nb != ob) atomicAdd(&g_acc[j], nb ? hc[k] : -hc[k]);
        }
    }
}

// ---------------------------------------------------------------- kernel 4: mod, gather, map
__global__ __launch_bounds__(256) void finalize_kernel(const int* __restrict__ table,
                                                       float* __restrict__ out)
{
    int j = blockIdx.x * 256 + threadIdx.x;
    if (j < B_N) {
        int idx = g_acc[j] & TABLE_MASK;
        float cp1 = (float)table[idx] + 1.0f;
        out[j] = 1.0f / (cp1 * cp1);
    }
}

// ---------------------------------------------------------------- launch
extern "C" void kernel_launch(void* const* d_in, const int* in_sizes, int n_in,
                              void* d_out, int out_size)
{
    const float* states  = (const float*)d_in[0];
    const float* actions = (const float*)d_in[1];
    const float* A       = (const float*)d_in[2];
    const float* b       = (const float*)d_in[3];
    const int*   table   = (const int*)  d_in[4];
    const int*   hc      = (const int*)  d_in[5];
    float* out = (float*)d_out;

    static int attr_set = 0;            // host-side only; device work identical every call
    if (!attr_set) {
        cudaFuncSetAttribute(gemm_tc, cudaFuncAttributeMaxDynamicSharedMemorySize, DYNSMEM);
        attr_set = 1;
    }

    split_kernel<<<(XHALF + AOCT + 255) / 256, 256>>>(states, actions, A);

    dim3 grid(K_N / BN, B_N / BM);      // (64, 16) = 1024 CTAs
    gemm_tc<<<grid, 256, DYNSMEM>>>(b, hc);

    fixup_kernel<<<148, 256>>>(states, actions, A, b, hc);

    finalize_kernel<<<(B_N + 255) / 256, 256>>>(table, out);
}

// round 17
// speedup vs baseline: 1.1573x; 1.1573x over previous
#include <cuda_runtime.h>
#include <cuda_fp16.h>
#include <cstdint>

// ---------------------------------------------------------------- dims
#define B_N   2048
#define D_IN  2047
#define NIN   2048
#define K_N   4096
#define TABLE_MASK ((1 << 22) - 1)

#define BM 128
#define BN 128
#define BK 64
#define NCHUNK (NIN / BK)          // 32
#define XPLANE (B_N * NIN)
#define APLANE (K_N * NIN)

#define TILE_BYTES 16384           // 128 rows x 128 B (XOR swizzle, no pad)
#define STAGEB (2 * TILE_BYTES)    // X + A = 32768 B
#define NSTAGE 3
#define DYNSMEM (NSTAGE * STAGEB)  // 98304 B

#define TH 0.15f

// ---------------------------------------------------------------- scratch
// Pre-tiled, pre-swizzled fp16 operands (contiguous 16 KB per (tile, chunk)):
//   byte(row, colh) = row*128 + (((colh>>3) ^ (row&7))<<4) + ((colh&7)<<1)
__device__ __align__(128) uint8_t g_Xt[16u * 32u * TILE_BYTES]; // 8 MB  [jt][ch][tile]
__device__ __align__(128) uint8_t g_At[32u * 32u * TILE_BYTES]; // 16 MB [kt][ch][tile]
__device__ int g_acc[B_N];

// ---------------------------------------------------------------- helpers
__device__ __forceinline__ uint32_t smem_u32(const void* p) {
    uint32_t a;
    asm("{ .reg .u64 t; cvta.to.shared.u64 t, %1; cvt.u32.u64 %0, t; }" : "=r"(a) : "l"(p));
    return a;
}
__device__ __forceinline__ void mbar_init(uint32_t mb, uint32_t cnt) {
    asm volatile("mbarrier.init.shared.b64 [%0], %1;" :: "r"(mb), "r"(cnt) : "memory");
}
__device__ __forceinline__ void mbar_expect_tx(uint32_t mb, uint32_t bytes) {
    asm volatile("mbarrier.arrive.expect_tx.shared.b64 _, [%0], %1;"
                 :: "r"(mb), "r"(bytes) : "memory");
}
__device__ __forceinline__ void mbar_wait(uint32_t mb, uint32_t parity) {
    asm volatile(
        "{\n\t.reg .pred P;\n"
        "W%=:\n\tmbarrier.try_wait.parity.shared.b64 P, [%0], %1;\n"
        "\t@!P bra W%=;\n\t}"
        :: "r"(mb), "r"(parity) : "memory");
}
__device__ __forceinline__ void bulk_g2s(uint32_t dst, const void* src,
                                         uint32_t bytes, uint32_t mb) {
    asm volatile(
        "cp.async.bulk.shared::cluster.global.mbarrier::complete_tx::bytes "
        "[%0], [%1], %2, [%3];"
        :: "r"(dst), "l"(src), "r"(bytes), "r"(mb) : "memory");
}
__device__ __forceinline__ void ldm_x4(uint32_t* r, uint32_t addr) {
    asm volatile("ldmatrix.sync.aligned.m8n8.x4.shared.b16 {%0,%1,%2,%3}, [%4];"
                 : "=r"(r[0]), "=r"(r[1]), "=r"(r[2]), "=r"(r[3]) : "r"(addr));
}
__device__ __forceinline__ void mma16816(float* d, const uint32_t* a, uint32_t b0, uint32_t b1) {
    asm volatile("mma.sync.aligned.m16n8k16.row.col.f32.f16.f16.f32 "
                 "{%0,%1,%2,%3},{%4,%5,%6,%7},{%8,%9},{%0,%1,%2,%3};"
                 : "+f"(d[0]), "+f"(d[1]), "+f"(d[2]), "+f"(d[3])
                 : "r"(a[0]), "r"(a[1]), "r"(a[2]), "r"(a[3]), "r"(b0), "r"(b1));
}

// ---------------------------------------------------------------- kernel 1: pack + fp16 convert into tiled/swizzled layout
#define XHALF (XPLANE / 2)
#define AOCT  (APLANE / 8)

__global__ __launch_bounds__(256) void split_kernel(const float* __restrict__ states,
                                                    const float* __restrict__ actions,
                                                    const float* __restrict__ A)
{
    unsigned t = blockIdx.x * 256u + threadIdx.x;
    if (t < B_N) g_acc[t] = 0;

    if (t < XHALF) {
        unsigned j  = t >> 10;
        unsigned d  = (t & 1023u) << 1;
        float f0 = states[j * D_IN + d];                               // d <= 2046
        float f1 = (d + 1 < D_IN) ? states[j * D_IN + d + 1] : actions[j];
        __half2 h = __halves2half2(__float2half_rn(f0), __float2half_rn(f1));
        unsigned jt = j >> 7, row = j & 127u;
        unsigned ch = d >> 6, colh = d & 63u;
        unsigned off = ((jt * 32u + ch) << 14)
                     + row * 128u
                     + (((colh >> 3) ^ (row & 7u)) << 4)
                     + ((colh & 7u) << 1);
        *(uint32_t*)(g_Xt + off) = *(uint32_t*)&h;
    } else {
        unsigned e = t - XHALF;
        if (e < AOCT) {
            unsigned k   = e >> 8;
            unsigned d8  = (e & 255u) << 3;
            const float4* src = (const float4*)(A + ((size_t)k << 11) + d8);
            float4 v0 = src[0], v1 = src[1];
            __half2 h0 = __halves2half2(__float2half_rn(v0.x), __float2half_rn(v0.y));
            __half2 h1 = __halves2half2(__float2half_rn(v0.z), __float2half_rn(v0.w));
            __half2 h2 = __halves2half2(__float2half_rn(v1.x), __float2half_rn(v1.y));
            __half2 h3 = __halves2half2(__float2half_rn(v1.z), __float2half_rn(v1.w));
            uint4 o;
            o.x = *(uint32_t*)&h0; o.y = *(uint32_t*)&h1;
            o.z = *(uint32_t*)&h2; o.w = *(uint32_t*)&h3;
            unsigned kt = k >> 7, row = k & 127u;
            unsigned ch = d8 >> 6, u = (d8 >> 3) & 7u;
            unsigned off = ((kt * 32u + ch) << 14)
                         + row * 128u
                         + ((u ^ (row & 7u)) << 4);
            *(uint4*)(g_At + off) = o;
        }
    }
}

// ---------------------------------------------------------------- kernel 2: fp16 HMMA GEMM + sign + hash + FUSED exact fixup
// Mainloop byte-identical to the 204.8us R13 kernel. Epilogue: for each
// |C+b|<TH element, the warp cooperatively recomputes the exact fp32 dot
// (same fmaf/reduce order as the separate fixup kernel -> bit-identical).
__global__ __launch_bounds__(256, 2) void gemm_tc(const float* __restrict__ b,
                                                  const int*   __restrict__ hc,
                                                  const float* __restrict__ states,
                                                  const float* __restrict__ actions,
                                                  const float* __restrict__ Ag)
{
    extern __shared__ __align__(128) unsigned char dynsmem[];
    __shared__ __align__(8) uint64_t s_mbar[NSTAGE];

    const uint32_t sbase = smem_u32(dynsmem);
    const uint32_t mb0   = smem_u32(&s_mbar[0]);

    const int tid  = threadIdx.x;
    const int wid  = tid >> 5;
    const int lane = tid & 31;
    const int wm   = wid & 1;          // 2 warps over M
    const int wn   = wid >> 1;         // 4 warps over N
    const int jt   = blockIdx.y;
    const int kt   = blockIdx.x;
    const int jBase = jt * BM;
    const int kBase = kt * BN;

    const int laneRow = (lane & 7) + ((lane >> 3) & 1) * 8;
    const int hi      = lane >> 4;     // 0/1: 16B-unit select within k16 slice

    float c[4][4][4];
    #pragma unroll
    for (int mi = 0; mi < 4; ++mi)
        #pragma unroll
        for (int ni = 0; ni < 4; ++ni)
            #pragma unroll
            for (int e = 0; e < 4; ++e) c[mi][ni][e] = 0.f;

    if (tid == 0) {
        #pragma unroll
        for (int s = 0; s < NSTAGE; ++s) mbar_init(mb0 + 8u * s, 1);
    }
    __syncthreads();
    if (tid == 0) asm volatile("fence.proxy.async.shared::cta;" ::: "memory");

    auto issue = [&](int ch, int s) {   // tid 0 only
        const uint32_t mb = mb0 + 8u * (uint32_t)s;
        const uint32_t dx = sbase + (uint32_t)s * STAGEB;
        mbar_expect_tx(mb, STAGEB);
        bulk_g2s(dx,              g_Xt + ((size_t)(jt * 32 + ch) << 14), TILE_BYTES, mb);
        bulk_g2s(dx + TILE_BYTES, g_At + ((size_t)(kt * 32 + ch) << 14), TILE_BYTES, mb);
    };

    if (tid == 0) { issue(0, 0); issue(1, 1); }

    for (int ch = 0; ch < NCHUNK; ++ch) {
        const int st = ch % NSTAGE;
        mbar_wait(mb0 + 8u * (uint32_t)st, (uint32_t)((ch / NSTAGE) & 1));
        __syncthreads();                          // all warps done with stage (ch-1)%3
        if (ch + 2 < NCHUNK && tid == 0)
            issue(ch + 2, (ch + 2) % NSTAGE);     // = stage (ch-1)%3, safe post-sync

        const uint32_t xt = sbase + (uint32_t)st * STAGEB;
        const uint32_t at = xt + TILE_BYTES;
        #pragma unroll
        for (int k16 = 0; k16 < 4; ++k16) {       // BK=64 -> 4 k16 slices
            const int u = k16 * 2 + hi;
            uint32_t af[4][4], bf[2][4];
            #pragma unroll
            for (int mi = 0; mi < 4; ++mi) {
                const int r = wm * 64 + mi * 16 + laneRow;
                ldm_x4(af[mi], xt + (uint32_t)(r * 128 + ((u ^ (r & 7)) << 4)));
            }
            #pragma unroll
            for (int nh = 0; nh < 2; ++nh) {
                const int r = wn * 32 + nh * 16 + laneRow;
                ldm_x4(bf[nh], at + (uint32_t)(r * 128 + ((u ^ (r & 7)) << 4)));
            }
            #pragma unroll
            for (int mi = 0; mi < 4; ++mi)
                #pragma unroll
                for (int ni = 0; ni < 4; ++ni)
                    mma16816(c[mi][ni], af[mi], bf[ni >> 1][ni & 1], bf[ni >> 1][(ni & 1) + 2]);
        }
    }

    // ---- epilogue: sign, hash-select, reduce, atomic; flagged elements fixed
    // exactly in-place by warp-cooperative fp32 dots.
    const int g  = lane >> 2;
    const int t4 = lane & 3;
    int khc[8];
    #pragma unroll
    for (int ni = 0; ni < 4; ++ni)
        #pragma unroll
        for (int e = 0; e < 2; ++e)
            khc[ni * 2 + e] = __ldg(&hc[kBase + wn * 32 + ni * 8 + t4 * 2 + e]);

    #pragma unroll
    for (int mi = 0; mi < 4; ++mi) {
        #pragma unroll
        for (int half = 0; half < 2; ++half) {
            const int j = jBase + wm * 64 + mi * 16 + half * 8 + g;
            const float bias = __ldg(&b[j]);
            int local = 0;
            #pragma unroll
            for (int ni = 0; ni < 4; ++ni) {
                #pragma unroll
                for (int e = 0; e < 2; ++e) {
                    const float v = c[mi][ni][half * 2 + e] + bias;
                    const int bit = v > 0.f;
                    if (bit) local += khc[ni * 2 + e];

                    // ---- fused exact fixup (rare: ~22k elements chip-wide)
                    unsigned m = __ballot_sync(0xFFFFFFFFu, fabsf(v) < TH);
                    while (m) {
                        const int src = __ffs(m) - 1;
                        m &= m - 1;
                        // j,k of the flagged element derive from src's (g,t4)
                        const int js = jBase + wm * 64 + mi * 16 + half * 8 + (src >> 2);
                        const int ks = kBase + wn * 32 + ni * 8 + (src & 3) * 2 + e;
                        const int bs = __shfl_sync(0xFFFFFFFFu, bit, src);
                        // exact dot, SAME fmaf/reduce order as the proven fixup kernel
                        const float*  xr = states + (size_t)js * D_IN;
                        const float4* ar = (const float4*)(Ag + (size_t)ks * NIN);
                        const float   act = actions[js];
                        float s = 0.f;
                        #pragma unroll 4
                        for (int d = lane; d < NIN / 4; d += 32) {
                            const int dd = d << 2;
                            float4 av = ar[d];
                            float x0 = xr[dd + 0];
                            float x1 = xr[dd + 1];
                            float x2 = xr[dd + 2];
                            float x3 = (dd + 3 < D_IN) ? xr[dd + 3] : act;
                            s = fmaf(x0, av.x, s);
                            s = fmaf(x1, av.y, s);
                            s = fmaf(x2, av.z, s);
                            s = fmaf(x3, av.w, s);
                        }
                        #pragma unroll
                        for (int o = 16; o; o >>= 1)
                            s += __shfl_xor_sync(0xFFFFFFFFu, s, o);
                        if (lane == 0) {
                            const int nb = (s + b[js]) > 0.f;
                            if (nb != bs)
                                atomicAdd(&g_acc[js], nb ? __ldg(&hc[ks]) : -__ldg(&hc[ks]));
                        }
                    }
                }
            }
            local += __shfl_xor_sync(0xFFFFFFFFu, local, 1);
            local += __shfl_xor_sync(0xFFFFFFFFu, local, 2);
            if (t4 == 0) atomicAdd(&g_acc[j], local);
        }
    }
}

// ---------------------------------------------------------------- kernel 3: mod, gather, map
__global__ __launch_bounds__(256) void finalize_kernel(const int* __restrict__ table,
                                                       float* __restrict__ out)
{
    int j = blockIdx.x * 256 + threadIdx.x;
    if (j < B_N) {
        int idx = g_acc[j] & TABLE_MASK;
        float cp1 = (float)table[idx] + 1.0f;
        out[j] = 1.0f / (cp1 * cp1);
    }
}

// ---------------------------------------------------------------- launch
extern "C" void kernel_launch(void* const* d_in, const int* in_sizes, int n_in,
                              void* d_out, int out_size)
{
    const float* states  = (const float*)d_in[0];
    const float* actions = (const float*)d_in[1];
    const float* A       = (const float*)d_in[2];
    const float* b       = (const float*)d_in[3];
    const int*   table   = (const int*)  d_in[4];
    const int*   hc      = (const int*)  d_in[5];
    float* out = (float*)d_out;

    static int attr_set = 0;            // host-side only; device work identical every call
    if (!attr_set) {
        cudaFuncSetAttribute(gemm_tc, cudaFuncAttributeMaxDynamicSharedMemorySize, DYNSMEM);
        attr_set = 1;
    }

    split_kernel<<<(XHALF + AOCT + 255) / 256, 256>>>(states, actions, A);

    dim3 grid(K_N / BN, B_N / BM);      // (32, 16) = 512 CTAs
    gemm_tc<<<grid, 256, DYNSMEM>>>(b, hc, states, actions, A);

    finalize_kernel<<<(B_N + 255) / 256, 256>>>(table, out);
}